// round 10
// baseline (speedup 1.0000x reference)
#include <cuda_runtime.h>

// ---------------------------------------------------------------------------
// out[i, :32] = sum_m sum_{j: t2m_j <= t1_i} (Q_i . Km_j) * Vm_j[:32]
//   Q = mlp3(m1, WQ); K_m = mlp3(m_m, WK[m]); V_m = m_m[:, :32]
// ---------------------------------------------------------------------------

#define T1        4096
#define TOTK      22528            // 4096+6144+8192+4096
#define CBLK      64               // key block size
#define NOBLK     352              // total key blocks (64+96+128+64)
#define NSTATE    356              // exclusive prefix states (nb+1 per modality)
#define NTILE     128              // query tiles of 32

typedef unsigned long long u64;

__device__ __forceinline__ u64 pk2(float lo, float hi) {
    u64 r; asm("mov.b64 %0,{%1,%2};" : "=l"(r) : "f"(lo), "f"(hi)); return r;
}
__device__ __forceinline__ void upk2(u64 v, float& lo, float& hi) {
    asm("mov.b64 {%0,%1},%2;" : "=f"(lo), "=f"(hi) : "l"(v));
}
__device__ __forceinline__ void ffma2(u64& d, u64 a, u64 b) {
    asm("fma.rn.f32x2 %0,%1,%2,%0;" : "+l"(d) : "l"(a), "l"(b));
}

// scratch (no allocations allowed)
__device__ float g_Q[T1 * 64];
__device__ float g_K[TOTK * 64];
__device__ float g_t2[TOTK];
__device__ float g_O[NOBLK * 2048];    // per-block sums  K^T V  (64 x 32)
__device__ float g_S[NSTATE * 2048];   // exclusive prefix states
__device__ float g_P[4][T1 * 32];      // per-modality partial outputs
__device__ int   g_cnt[NTILE][4][2];

__constant__ int c_T2[4]    = {4096, 6144, 8192, 4096};
__constant__ int c_KOFF[4]  = {0, 4096, 10240, 18432};
__constant__ int c_NB[4]    = {64, 96, 128, 64};
__constant__ int c_OOFF[5]  = {0, 64, 160, 288, 352};
__constant__ int c_SOFF[4]  = {0, 65, 162, 291};

// ---------------------------------------------------------------------------
// Kernel 1: fused 3-layer MLP + (for K tasks) per-block outer-product sums
// O_b = K_blk^T V_blk and t2 extraction. (Round-8 proven config.)
// ---------------------------------------------------------------------------
__global__ void __launch_bounds__(256) mlp_kernel(
    const float* __restrict__ m1, const float* __restrict__ m2,
    const float* __restrict__ m3, const float* __restrict__ m4,
    const float* __restrict__ WQ_w, const float* __restrict__ WQ_b,
    const float* __restrict__ WK_w, const float* __restrict__ WK_b)
{
    __shared__ float Hs[64][68];   // [k][row] transposed activations; later V
    __shared__ float Ws[64][68];   // [k][col] weights; later K tile [j][d]
    __shared__ float bs[64];

    const int task = blockIdx.y;
    const int rowsTab[5] = {4096, 4096, 6144, 8192, 4096};
    const int rows = rowsTab[task];
    const int row0 = blockIdx.x * 64;
    if (row0 >= rows) return;

    const float* X;
    if (task <= 1)      X = m1;
    else if (task == 2) X = m2;
    else if (task == 3) X = m3;
    else                X = m4;

    const float* Wb; const float* bb; float* out;
    if (task == 0) { Wb = WQ_w; bb = WQ_b; out = g_Q; }
    else {
        int m = task - 1;
        Wb = WK_w + m * 3 * 4096;
        bb = WK_b + m * 192;
        out = g_K + c_KOFF[m] * 64;
    }

    const int tid = threadIdx.x;
    for (int idx = tid; idx < 4096; idx += 256) {
        int r = idx >> 6, c = idx & 63;
        Hs[c][r] = X[(row0 + r) * 64 + c];
    }

    const int r0 = (tid & 15) * 4;     // 16 row groups
    const int c0 = (tid >> 4) * 4;     // 16 col groups

    for (int l = 0; l < 3; l++) {
        for (int idx = tid; idx < 4096; idx += 256)
            Ws[idx >> 6][idx & 63] = Wb[l * 4096 + idx];
        if (tid < 64) bs[tid] = bb[l * 64 + tid];
        __syncthreads();

        u64 acc[4][2];   // [row][col-pair]
        #pragma unroll
        for (int rr = 0; rr < 4; rr++)
            #pragma unroll
            for (int cp = 0; cp < 2; cp++)
                acc[rr][cp] = pk2(bs[c0 + 2 * cp], bs[c0 + 2 * cp + 1]);

        #pragma unroll 8
        for (int k = 0; k < 64; k++) {
            float4 h = *(const float4*)&Hs[k][r0];
            ulonglong2 w2 = *(const ulonglong2*)&Ws[k][c0];
            u64 hd0 = pk2(h.x, h.x), hd1 = pk2(h.y, h.y);
            u64 hd2 = pk2(h.z, h.z), hd3 = pk2(h.w, h.w);
            ffma2(acc[0][0], hd0, w2.x); ffma2(acc[0][1], hd0, w2.y);
            ffma2(acc[1][0], hd1, w2.x); ffma2(acc[1][1], hd1, w2.y);
            ffma2(acc[2][0], hd2, w2.x); ffma2(acc[2][1], hd2, w2.y);
            ffma2(acc[3][0], hd3, w2.x); ffma2(acc[3][1], hd3, w2.y);
        }

        float a[4][4];
        #pragma unroll
        for (int rr = 0; rr < 4; rr++)
            #pragma unroll
            for (int cp = 0; cp < 2; cp++)
                upk2(acc[rr][cp], a[rr][2 * cp], a[rr][2 * cp + 1]);

        if (l < 2) {
            #pragma unroll
            for (int rr = 0; rr < 4; rr++)
                #pragma unroll
                for (int cc = 0; cc < 4; cc++) a[rr][cc] = fmaxf(a[rr][cc], 0.0f);
        }
        __syncthreads();

        if (l < 2) {
            #pragma unroll
            for (int cc = 0; cc < 4; cc++) {
                float4 v = make_float4(a[0][cc], a[1][cc], a[2][cc], a[3][cc]);
                *(float4*)&Hs[c0 + cc][r0] = v;
            }
        } else {
            #pragma unroll
            for (int rr = 0; rr < 4; rr++) {
                float4 v = make_float4(a[rr][0], a[rr][1], a[rr][2], a[rr][3]);
                *(float4*)&out[(row0 + r0 + rr) * 64 + c0] = v;
                if (task > 0) *(float4*)&Ws[r0 + rr][c0] = v;
            }
        }
    }

    if (task == 0) return;

    // ---------------- fused blocksum: O_b = K^T V, t2 extraction ----------
    const int m = task - 1;
    for (int idx = tid; idx < 2048; idx += 256) {
        int j = idx >> 5, e = idx & 31;
        Hs[j][e] = X[(row0 + j) * 64 + e];
    }
    if (tid < 64) g_t2[c_KOFF[m] + row0 + tid] = X[(row0 + tid) * 64 + 63];
    __syncthreads();

    const int d1 = tid & 63;
    const int gg = tid >> 6;   // 0..3 -> e0 = gg*8
    u64 acc2[4] = {0ULL, 0ULL, 0ULL, 0ULL};

    #pragma unroll 8
    for (int j = 0; j < CBLK; j++) {
        float kv = Ws[j][d1];
        u64 kd = pk2(kv, kv);
        ulonglong2 va = *(const ulonglong2*)&Hs[j][gg * 8];
        ulonglong2 vb = *(const ulonglong2*)&Hs[j][gg * 8 + 4];
        ffma2(acc2[0], kd, va.x); ffma2(acc2[1], kd, va.y);
        ffma2(acc2[2], kd, vb.x); ffma2(acc2[3], kd, vb.y);
    }
    float a2[8];
    upk2(acc2[0], a2[0], a2[1]); upk2(acc2[1], a2[2], a2[3]);
    upk2(acc2[2], a2[4], a2[5]); upk2(acc2[3], a2[6], a2[7]);
    const int blk = c_OOFF[m] + (row0 >> 6);
    float* o = &g_O[blk * 2048 + d1 * 32 + gg * 8];
    *(float4*)o       = make_float4(a2[0], a2[1], a2[2], a2[3]);
    *(float4*)(o + 4) = make_float4(a2[4], a2[5], a2[6], a2[7]);
}

// ---------------------------------------------------------------------------
// Kernel 2: warp-parallel exclusive scan + tile binary searches.
// ---------------------------------------------------------------------------
__global__ void __launch_bounds__(256) scan_search_kernel()
{
    const int blk = blockIdx.x;
    if (blk < 1024) {
        const int gw   = blk * 8 + (threadIdx.x >> 5);   // 0..8191
        const int lane = threadIdx.x & 31;
        const int m    = gw >> 11;
        const int el   = gw & 2047;
        const int nb   = c_NB[m];
        const int q    = nb >> 5;                        // 2,3,4,2
        const float* src = &g_O[c_OOFF[m] * 2048 + el];
        float* dst       = &g_S[c_SOFF[m] * 2048 + el];
        const int b0 = lane * q;

        float v[4];
        #pragma unroll
        for (int b = 0; b < 4; b++)
            v[b] = (b < q) ? src[(b0 + b) * 2048] : 0.0f;
        float s = 0.0f;
        #pragma unroll
        for (int b = 0; b < 4; b++) if (b < q) s += v[b];

        float incl = s;
        #pragma unroll
        for (int off = 1; off < 32; off <<= 1) {
            float t = __shfl_up_sync(0xffffffffu, incl, off);
            if (lane >= off) incl += t;
        }
        float run = incl - s;

        #pragma unroll
        for (int b = 0; b < 4; b++) {
            if (b < q) { dst[(b0 + b) * 2048] = run; run += v[b]; }
        }
        if (lane == 31) dst[nb * 2048] = run;
    } else {
        const int sid = (blk - 1024) * 256 + threadIdx.x;   // 0..1023
        const int tile = sid >> 3;
        const int m    = (sid >> 1) & 3;
        const int w    = sid & 1;
        const float target = g_t2[tile * 32 + (w ? 31 : 0)];
        const int ko = c_KOFF[m];
        int lo = 0, hi = c_T2[m];
        while (lo < hi) {
            int mid = (lo + hi) >> 1;
            if (g_t2[ko + mid] <= target) lo = mid + 1; else hi = mid;
        }
        g_cnt[tile][m][w] = lo;
    }
}

// ---------------------------------------------------------------------------
// Kernel 3: query kernel, transpose-free accumulation.
// One block = (32-query tile, modality). Warp g owns j-slice {g*8..g*8+7}
// of each 64-key chunk. Each thread keeps a FULL 32-wide output accumulator;
// V comes via uniform broadcast LDG from X (no Vs smem, no score smem, only
// 2 syncs per chunk). Cross-warp combine = one 3-round tree per block.
// ---------------------------------------------------------------------------
__global__ void __launch_bounds__(256) query_kernel(
    const float* __restrict__ m1, const float* __restrict__ m2,
    const float* __restrict__ m3, const float* __restrict__ m4)
{
    __shared__ float Qs[64][33];     // [d][i]
    __shared__ float Ss[2048];       // state [d*32+e]
    __shared__ float Ks[64 * 72];    // key chunk [d][j] (stride 72); later the
                                     // 4*32*36 tree-reduction buffer
    __shared__ float t2s[64];

    const int tid = threadIdx.x;
    const int i   = tid & 31;        // query (lane)
    const int g   = tid >> 5;        // warp id = j-group
    const int tile = blockIdx.x;
    const int m    = blockIdx.y;
    const int i0   = tile * 32;

    const float* X;
    if (m == 0) X = m1; else if (m == 1) X = m2; else if (m == 2) X = m3; else X = m4;
    const int ko = c_KOFF[m];

    const int cf = g_cnt[tile][m][0];
    const int cl = g_cnt[tile][m][1];
    const int B0 = cf >> 6;
    const int jstart = B0 << 6;
    const int jend = cl;

    for (int idx = tid; idx < 2048; idx += 256) {
        int r = idx >> 6, d = idx & 63;
        Qs[d][r] = g_Q[(i0 + r) * 64 + d];
    }
    const float* Sp = &g_S[(c_SOFF[m] + B0) * 2048];
    for (int idx = tid; idx < 2048; idx += 256) Ss[idx] = Sp[idx];
    const float t1i = g_t2[i0 + i];
    __syncthreads();

    u64 acc[16];   // full 32-e accumulator, pairs (2p, 2p+1)
    #pragma unroll
    for (int p = 0; p < 16; p++) acc[p] = 0ULL;

    // state matvec, distributed over g: this thread covers e = g*4 .. g*4+3
    {
        const int e0 = g * 4;
        #pragma unroll 8
        for (int d = 0; d < 64; d++) {
            float q = Qs[d][i];
            u64 qd = pk2(q, q);
            ulonglong2 s2 = *(const ulonglong2*)&Ss[d * 32 + e0];
            ffma2(acc[2 * g], qd, s2.x); ffma2(acc[2 * g + 1], qd, s2.y);
        }
    }

    const int j0 = g * 8;
    for (int jc = jstart; jc < jend; jc += 64) {
        const int nj = min(64, jend - jc);
        __syncthreads();   // prev chunk's Ks reads done
        for (int idx = tid; idx < 4096; idx += 256) {
            int j = idx >> 6, d = idx & 63;
            Ks[d * 72 + j] = (j < nj) ? g_K[(ko + jc + j) * 64 + d] : 0.0f;
        }
        if (tid < 64) t2s[tid] = (tid < nj) ? g_t2[ko + jc + tid] : 3.0e38f;
        __syncthreads();

        // scores: this warp computes j = j0 .. j0+7 for all 32 queries
        u64 s01 = 0ULL, s23 = 0ULL, s45 = 0ULL, s67 = 0ULL;
        #pragma unroll 8
        for (int d = 0; d < 64; d++) {
            float q = Qs[d][i];
            u64 qd = pk2(q, q);
            ulonglong2 ka = *(const ulonglong2*)&Ks[d * 72 + j0];
            ulonglong2 kb = *(const ulonglong2*)&Ks[d * 72 + j0 + 4];
            ffma2(s01, qd, ka.x); ffma2(s23, qd, ka.y);
            ffma2(s45, qd, kb.x); ffma2(s67, qd, kb.y);
        }
        float sv[8];
        upk2(s01, sv[0], sv[1]); upk2(s23, sv[2], sv[3]);
        upk2(s45, sv[4], sv[5]); upk2(s67, sv[6], sv[7]);

        // accumulate: acc[:] += s_j * V_j[:32], V via uniform broadcast LDG
        #pragma unroll
        for (int jj = 0; jj < 8; jj++) {
            float s = (t2s[j0 + jj] <= t1i) ? sv[jj] : 0.0f;
            u64 sd = pk2(s, s);
            const int jg = j0 + jj;
            const float* vp = (jg < nj) ? &X[(size_t)(jc + jg) * 64] : X;
            #pragma unroll
            for (int q = 0; q < 4; q++) {
                ulonglong2 v2 = *(const ulonglong2*)&vp[q * 8];
                ulonglong2 v3 = *(const ulonglong2*)&vp[q * 8 + 4];
                ffma2(acc[4 * q],     sd, v2.x);   // elems 8q..8q+1
                ffma2(acc[4 * q + 1], sd, v2.y);   // elems 8q+2..8q+3
                ffma2(acc[4 * q + 2], sd, v3.x);   // elems 8q+4..8q+5
                ffma2(acc[4 * q + 3], sd, v3.y);   // elems 8q+6..8q+7
            }
        }
    }

    // unpack accumulator
    float av[32];
    #pragma unroll
    for (int p = 0; p < 16; p++) upk2(acc[p], av[2 * p], av[2 * p + 1]);

    // 3-round tree reduction over g (8 -> 4 -> 2 -> 1) in the Ks buffer
    float* R = Ks;   // [4][32][36]
    __syncthreads();
    if (g >= 4) {
        float* r = &R[((g - 4) * 32 + i) * 36];
        #pragma unroll
        for (int q = 0; q < 8; q++)
            *(float4*)&r[q * 4] = make_float4(av[4*q], av[4*q+1], av[4*q+2], av[4*q+3]);
    }
    __syncthreads();
    if (g < 4) {
        const float* r = &R[(g * 32 + i) * 36];
        #pragma unroll
        for (int q = 0; q < 8; q++) {
            float4 x4 = *(const float4*)&r[q * 4];
            av[4*q] += x4.x; av[4*q+1] += x4.y; av[4*q+2] += x4.z; av[4*q+3] += x4.w;
        }
    }
    __syncthreads();
    if (g == 2 || g == 3) {
        float* r = &R[((g - 2) * 32 + i) * 36];
        #pragma unroll
        for (int q = 0; q < 8; q++)
            *(float4*)&r[q * 4] = make_float4(av[4*q], av[4*q+1], av[4*q+2], av[4*q+3]);
    }
    __syncthreads();
    if (g < 2) {
        const float* r = &R[(g * 32 + i) * 36];
        #pragma unroll
        for (int q = 0; q < 8; q++) {
            float4 x4 = *(const float4*)&r[q * 4];
            av[4*q] += x4.x; av[4*q+1] += x4.y; av[4*q+2] += x4.z; av[4*q+3] += x4.w;
        }
    }
    __syncthreads();
    if (g == 1) {
        float* r = &R[(0 * 32 + i) * 36];
        #pragma unroll
        for (int q = 0; q < 8; q++)
            *(float4*)&r[q * 4] = make_float4(av[4*q], av[4*q+1], av[4*q+2], av[4*q+3]);
    }
    __syncthreads();
    if (g == 0) {
        const float* r = &R[(0 * 32 + i) * 36];
        float* op = &g_P[m][(i0 + i) * 32];
        #pragma unroll
        for (int q = 0; q < 8; q++) {
            float4 x4 = *(const float4*)&r[q * 4];
            *(float4*)&op[q * 4] = make_float4(av[4*q] + x4.x, av[4*q+1] + x4.y,
                                               av[4*q+2] + x4.z, av[4*q+3] + x4.w);
        }
    }
}

// ---------------------------------------------------------------------------
// Kernel 4: sum the 4 per-modality partials into the output.
// ---------------------------------------------------------------------------
__global__ void __launch_bounds__(256) reduce_kernel(float* __restrict__ out)
{
    const int idx = (blockIdx.x * 256 + threadIdx.x);
    if (idx >= T1 * 32 / 4) return;
    float4 a = ((const float4*)g_P[0])[idx];
    float4 b = ((const float4*)g_P[1])[idx];
    float4 c = ((const float4*)g_P[2])[idx];
    float4 d = ((const float4*)g_P[3])[idx];
    float4 o;
    o.x = (a.x + b.x) + (c.x + d.x);
    o.y = (a.y + b.y) + (c.y + d.y);
    o.z = (a.z + b.z) + (c.z + d.z);
    o.w = (a.w + b.w) + (c.w + d.w);
    ((float4*)out)[idx] = o;
}

// ---------------------------------------------------------------------------
extern "C" void kernel_launch(void* const* d_in, const int* in_sizes, int n_in,
                              void* d_out, int out_size)
{
    const float* m1   = (const float*)d_in[0];
    const float* m2   = (const float*)d_in[1];
    const float* m3   = (const float*)d_in[2];
    const float* m4   = (const float*)d_in[3];
    const float* WQ_w = (const float*)d_in[4];
    const float* WQ_b = (const float*)d_in[5];
    const float* WK_w = (const float*)d_in[6];
    const float* WK_b = (const float*)d_in[7];
    float* out = (float*)d_out;

    mlp_kernel<<<dim3(128, 5), 256>>>(m1, m2, m3, m4, WQ_w, WQ_b, WK_w, WK_b);
    scan_search_kernel<<<1028, 256>>>();
    query_kernel<<<dim3(NTILE, 4), 256>>>(m1, m2, m3, m4);
    reduce_kernel<<<(T1 * 32 / 4 + 255) / 256, 256>>>(out);
}

// round 11
// speedup vs baseline: 1.1507x; 1.1507x over previous
#include <cuda_runtime.h>

// ---------------------------------------------------------------------------
// out[i, :32] = sum_m sum_{j: t2m_j <= t1_i} (Q_i . Km_j) * Vm_j[:32]
//   Q = mlp3(m1, WQ); K_m = mlp3(m_m, WK[m]); V_m = m_m[:, :32]
// ---------------------------------------------------------------------------

#define T1        4096
#define TOTK      22528            // 4096+6144+8192+4096
#define CBLK      64               // key block size
#define NOBLK     352              // total key blocks (64+96+128+64)
#define NSTATE    356              // exclusive prefix states (nb+1 per modality)
#define NTILE     128              // query tiles of 32

typedef unsigned long long u64;

__device__ __forceinline__ u64 pk2(float lo, float hi) {
    u64 r; asm("mov.b64 %0,{%1,%2};" : "=l"(r) : "f"(lo), "f"(hi)); return r;
}
__device__ __forceinline__ void upk2(u64 v, float& lo, float& hi) {
    asm("mov.b64 {%0,%1},%2;" : "=f"(lo), "=f"(hi) : "l"(v));
}
__device__ __forceinline__ void ffma2(u64& d, u64 a, u64 b) {
    asm("fma.rn.f32x2 %0,%1,%2,%0;" : "+l"(d) : "l"(a), "l"(b));
}

// scratch (no allocations allowed)
__device__ float g_Q[T1 * 64];
__device__ float g_K[TOTK * 64];
__device__ float g_t2[TOTK];
__device__ float g_O[NOBLK * 2048];    // per-block sums  K^T V  (64 x 32)
__device__ float g_S[NSTATE * 2048];   // exclusive prefix states
__device__ float g_P[4][T1 * 32];      // per-modality partial outputs
__device__ int   g_cnt[NTILE][4][2];

__constant__ int c_T2[4]    = {4096, 6144, 8192, 4096};
__constant__ int c_KOFF[4]  = {0, 4096, 10240, 18432};
__constant__ int c_NB[4]    = {64, 96, 128, 64};
__constant__ int c_OOFF[5]  = {0, 64, 160, 288, 352};
__constant__ int c_SOFF[4]  = {0, 65, 162, 291};

// ---------------------------------------------------------------------------
// Kernel 1: fused 3-layer MLP + (for K tasks) per-block outer-product sums
// O_b = K_blk^T V_blk and t2 extraction. (Round-8 proven config.)
// ---------------------------------------------------------------------------
__global__ void __launch_bounds__(256) mlp_kernel(
    const float* __restrict__ m1, const float* __restrict__ m2,
    const float* __restrict__ m3, const float* __restrict__ m4,
    const float* __restrict__ WQ_w, const float* __restrict__ WQ_b,
    const float* __restrict__ WK_w, const float* __restrict__ WK_b)
{
    __shared__ float Hs[64][68];   // [k][row] transposed activations; later V
    __shared__ float Ws[64][68];   // [k][col] weights; later K tile [j][d]
    __shared__ float bs[64];

    const int task = blockIdx.y;
    const int rowsTab[5] = {4096, 4096, 6144, 8192, 4096};
    const int rows = rowsTab[task];
    const int row0 = blockIdx.x * 64;
    if (row0 >= rows) return;

    const float* X;
    if (task <= 1)      X = m1;
    else if (task == 2) X = m2;
    else if (task == 3) X = m3;
    else                X = m4;

    const float* Wb; const float* bb; float* out;
    if (task == 0) { Wb = WQ_w; bb = WQ_b; out = g_Q; }
    else {
        int m = task - 1;
        Wb = WK_w + m * 3 * 4096;
        bb = WK_b + m * 192;
        out = g_K + c_KOFF[m] * 64;
    }

    const int tid = threadIdx.x;
    for (int idx = tid; idx < 4096; idx += 256) {
        int r = idx >> 6, c = idx & 63;
        Hs[c][r] = X[(row0 + r) * 64 + c];
    }

    const int r0 = (tid & 15) * 4;     // 16 row groups
    const int c0 = (tid >> 4) * 4;     // 16 col groups

    for (int l = 0; l < 3; l++) {
        for (int idx = tid; idx < 4096; idx += 256)
            Ws[idx >> 6][idx & 63] = Wb[l * 4096 + idx];
        if (tid < 64) bs[tid] = bb[l * 64 + tid];
        __syncthreads();

        u64 acc[4][2];   // [row][col-pair]
        #pragma unroll
        for (int rr = 0; rr < 4; rr++)
            #pragma unroll
            for (int cp = 0; cp < 2; cp++)
                acc[rr][cp] = pk2(bs[c0 + 2 * cp], bs[c0 + 2 * cp + 1]);

        #pragma unroll 8
        for (int k = 0; k < 64; k++) {
            float4 h = *(const float4*)&Hs[k][r0];
            ulonglong2 w2 = *(const ulonglong2*)&Ws[k][c0];
            u64 hd0 = pk2(h.x, h.x), hd1 = pk2(h.y, h.y);
            u64 hd2 = pk2(h.z, h.z), hd3 = pk2(h.w, h.w);
            ffma2(acc[0][0], hd0, w2.x); ffma2(acc[0][1], hd0, w2.y);
            ffma2(acc[1][0], hd1, w2.x); ffma2(acc[1][1], hd1, w2.y);
            ffma2(acc[2][0], hd2, w2.x); ffma2(acc[2][1], hd2, w2.y);
            ffma2(acc[3][0], hd3, w2.x); ffma2(acc[3][1], hd3, w2.y);
        }

        float a[4][4];
        #pragma unroll
        for (int rr = 0; rr < 4; rr++)
            #pragma unroll
            for (int cp = 0; cp < 2; cp++)
                upk2(acc[rr][cp], a[rr][2 * cp], a[rr][2 * cp + 1]);

        if (l < 2) {
            #pragma unroll
            for (int rr = 0; rr < 4; rr++)
                #pragma unroll
                for (int cc = 0; cc < 4; cc++) a[rr][cc] = fmaxf(a[rr][cc], 0.0f);
        }
        __syncthreads();

        if (l < 2) {
            #pragma unroll
            for (int cc = 0; cc < 4; cc++) {
                float4 v = make_float4(a[0][cc], a[1][cc], a[2][cc], a[3][cc]);
                *(float4*)&Hs[c0 + cc][r0] = v;
            }
        } else {
            #pragma unroll
            for (int rr = 0; rr < 4; rr++) {
                float4 v = make_float4(a[rr][0], a[rr][1], a[rr][2], a[rr][3]);
                *(float4*)&out[(row0 + r0 + rr) * 64 + c0] = v;
                if (task > 0) *(float4*)&Ws[r0 + rr][c0] = v;
            }
        }
    }

    if (task == 0) return;

    // ---------------- fused blocksum: O_b = K^T V, t2 extraction ----------
    const int m = task - 1;
    for (int idx = tid; idx < 2048; idx += 256) {
        int j = idx >> 5, e = idx & 31;
        Hs[j][e] = X[(row0 + j) * 64 + e];
    }
    if (tid < 64) g_t2[c_KOFF[m] + row0 + tid] = X[(row0 + tid) * 64 + 63];
    __syncthreads();

    const int d1 = tid & 63;
    const int gg = tid >> 6;   // 0..3 -> e0 = gg*8
    u64 acc2[4] = {0ULL, 0ULL, 0ULL, 0ULL};

    #pragma unroll 8
    for (int j = 0; j < CBLK; j++) {
        float kv = Ws[j][d1];
        u64 kd = pk2(kv, kv);
        ulonglong2 va = *(const ulonglong2*)&Hs[j][gg * 8];
        ulonglong2 vb = *(const ulonglong2*)&Hs[j][gg * 8 + 4];
        ffma2(acc2[0], kd, va.x); ffma2(acc2[1], kd, va.y);
        ffma2(acc2[2], kd, vb.x); ffma2(acc2[3], kd, vb.y);
    }
    float a2[8];
    upk2(acc2[0], a2[0], a2[1]); upk2(acc2[1], a2[2], a2[3]);
    upk2(acc2[2], a2[4], a2[5]); upk2(acc2[3], a2[6], a2[7]);
    const int blk = c_OOFF[m] + (row0 >> 6);
    float* o = &g_O[blk * 2048 + d1 * 32 + gg * 8];
    *(float4*)o       = make_float4(a2[0], a2[1], a2[2], a2[3]);
    *(float4*)(o + 4) = make_float4(a2[4], a2[5], a2[6], a2[7]);
}

// ---------------------------------------------------------------------------
// Kernel 2: warp-parallel exclusive scan + tile binary searches.
// ---------------------------------------------------------------------------
__global__ void __launch_bounds__(256) scan_search_kernel()
{
    const int blk = blockIdx.x;
    if (blk < 1024) {
        const int gw   = blk * 8 + (threadIdx.x >> 5);   // 0..8191
        const int lane = threadIdx.x & 31;
        const int m    = gw >> 11;
        const int el   = gw & 2047;
        const int nb   = c_NB[m];
        const int q    = nb >> 5;                        // 2,3,4,2
        const float* src = &g_O[c_OOFF[m] * 2048 + el];
        float* dst       = &g_S[c_SOFF[m] * 2048 + el];
        const int b0 = lane * q;

        float v[4];
        #pragma unroll
        for (int b = 0; b < 4; b++)
            v[b] = (b < q) ? src[(b0 + b) * 2048] : 0.0f;
        float s = 0.0f;
        #pragma unroll
        for (int b = 0; b < 4; b++) if (b < q) s += v[b];

        float incl = s;
        #pragma unroll
        for (int off = 1; off < 32; off <<= 1) {
            float t = __shfl_up_sync(0xffffffffu, incl, off);
            if (lane >= off) incl += t;
        }
        float run = incl - s;

        #pragma unroll
        for (int b = 0; b < 4; b++) {
            if (b < q) { dst[(b0 + b) * 2048] = run; run += v[b]; }
        }
        if (lane == 31) dst[nb * 2048] = run;
    } else {
        const int sid = (blk - 1024) * 256 + threadIdx.x;   // 0..1023
        const int tile = sid >> 3;
        const int m    = (sid >> 1) & 3;
        const int w    = sid & 1;
        const float target = g_t2[tile * 32 + (w ? 31 : 0)];
        const int ko = c_KOFF[m];
        int lo = 0, hi = c_T2[m];
        while (lo < hi) {
            int mid = (lo + hi) >> 1;
            if (g_t2[ko + mid] <= target) lo = mid + 1; else hi = mid;
        }
        g_cnt[tile][m][w] = lo;
    }
}

// ---------------------------------------------------------------------------
// Kernel 3: query kernel, pair-packed. One block = (32-query tile, modality).
// Layouts: Qs[i][d], Ks[j][d] (straight copies), Ss2[e][d], Vs2[e][j],
// sc[i][j] (all stride 68, conflict-free). Score loop packs over d, accumulate
// packs over j; zero mov.b64 in hot loops. Warp g: scores j=g*8..+7,
// accumulates e=g*4..+3 over ALL j (no cross-warp reduction).
// ---------------------------------------------------------------------------
__global__ void __launch_bounds__(256) query_kernel(
    const float* __restrict__ m1, const float* __restrict__ m2,
    const float* __restrict__ m3, const float* __restrict__ m4)
{
    __shared__ float Qs [32][68];    // [i][d]
    __shared__ float Ss2[32][68];    // state transposed [e][d]
    __shared__ float Ks [64][68];    // keys [j][d]
    __shared__ float Vs2[32][68];    // values transposed [e][j]
    __shared__ float sc [32][68];    // scores [i][j]
    __shared__ float t2s[64];

    const int tid = threadIdx.x;
    const int i   = tid & 31;        // query (lane)
    const int g   = tid >> 5;        // warp
    const int e0  = g * 4;           // e-slice for matvec/accumulate
    const int j0  = g * 8;           // j-slice for scores
    const int tile = blockIdx.x;
    const int m    = blockIdx.y;
    const int i0   = tile * 32;

    const float* X;
    if (m == 0) X = m1; else if (m == 1) X = m2; else if (m == 2) X = m3; else X = m4;
    const int ko = c_KOFF[m];

    const int cf = g_cnt[tile][m][0];
    const int cl = g_cnt[tile][m][1];
    const int B0 = cf >> 6;
    const int jstart = B0 << 6;
    const int jend = cl;

    // Qs: straight copy [i][d]
    for (int idx = tid; idx < 2048; idx += 256) {
        int r = idx >> 6, d = idx & 63;
        Qs[r][d] = g_Q[(i0 + r) * 64 + d];
    }
    // Ss2: transpose state [d*32+e] -> [e][d]
    const float* Sp = &g_S[(c_SOFF[m] + B0) * 2048];
    for (int idx = tid; idx < 2048; idx += 256) {
        int d = idx >> 5, e = idx & 31;
        Ss2[e][d] = Sp[idx];
    }
    const float t1i = g_t2[i0 + i];
    __syncthreads();

    // pair accumulators for e0..e0+3 (halves combined at the end)
    u64 accp[4] = {0ULL, 0ULL, 0ULL, 0ULL};

    // state matvec: acc[e] += sum_d Q[i][d] * S[d][e], packed over d
    #pragma unroll 4
    for (int dp = 0; dp < 16; dp++) {
        ulonglong2 q2 = *(const ulonglong2*)&Qs[i][dp * 4];
        #pragma unroll
        for (int e = 0; e < 4; e++) {
            ulonglong2 s2 = *(const ulonglong2*)&Ss2[e0 + e][dp * 4];
            ffma2(accp[e], q2.x, s2.x);
            ffma2(accp[e], q2.y, s2.y);
        }
    }

    for (int jc = jstart; jc < jend; jc += 64) {
        const int nj = min(64, jend - jc);
        __syncthreads();   // prev chunk's Ks/Vs2/sc reads done
        for (int idx = tid; idx < 4096; idx += 256) {
            int j = idx >> 6, d = idx & 63;
            Ks[j][d] = (j < nj) ? g_K[(ko + jc + j) * 64 + d] : 0.0f;
        }
        for (int idx = tid; idx < 2048; idx += 256) {
            int j = idx >> 5, e = idx & 31;
            Vs2[e][j] = (j < nj) ? X[(jc + j) * 64 + e] : 0.0f;
        }
        if (tid < 64) t2s[tid] = (tid < nj) ? g_t2[ko + jc + tid] : 3.0e38f;
        __syncthreads();

        // scores: warp g computes j0..j0+7 for its lane's query i, packed over d
        u64 sp[8];
        #pragma unroll
        for (int jj = 0; jj < 8; jj++) sp[jj] = 0ULL;
        #pragma unroll 4
        for (int dp = 0; dp < 16; dp++) {
            ulonglong2 q2 = *(const ulonglong2*)&Qs[i][dp * 4];
            #pragma unroll
            for (int jj = 0; jj < 8; jj++) {
                ulonglong2 k2 = *(const ulonglong2*)&Ks[j0 + jj][dp * 4];
                ffma2(sp[jj], q2.x, k2.x);
                ffma2(sp[jj], q2.y, k2.y);
            }
        }
        #pragma unroll
        for (int jj = 0; jj < 8; jj++) {
            float slo, shi;
            upk2(sp[jj], slo, shi);
            float s = slo + shi;
            sc[i][j0 + jj] = (t2s[j0 + jj] <= t1i) ? s : 0.0f;
        }
        __syncthreads();

        // accumulate: acc[e] += sum_j sc[i][j] * V[j][e], packed over j
        #pragma unroll 4
        for (int jp = 0; jp < 16; jp++) {
            ulonglong2 s2 = *(const ulonglong2*)&sc[i][jp * 4];
            #pragma unroll
            for (int e = 0; e < 4; e++) {
                ulonglong2 v2 = *(const ulonglong2*)&Vs2[e0 + e][jp * 4];
                ffma2(accp[e], s2.x, v2.x);
                ffma2(accp[e], s2.y, v2.y);
            }
        }
    }

    // collapse pair halves and write
    float av[4];
    #pragma unroll
    for (int e = 0; e < 4; e++) {
        float lo, hi;
        upk2(accp[e], lo, hi);
        av[e] = lo + hi;
    }
    *(float4*)&g_P[m][(i0 + i) * 32 + e0] = make_float4(av[0], av[1], av[2], av[3]);
}

// ---------------------------------------------------------------------------
// Kernel 4: sum the 4 per-modality partials into the output.
// ---------------------------------------------------------------------------
__global__ void __launch_bounds__(256) reduce_kernel(float* __restrict__ out)
{
    const int idx = (blockIdx.x * 256 + threadIdx.x);
    if (idx >= T1 * 32 / 4) return;
    float4 a = ((const float4*)g_P[0])[idx];
    float4 b = ((const float4*)g_P[1])[idx];
    float4 c = ((const float4*)g_P[2])[idx];
    float4 d = ((const float4*)g_P[3])[idx];
    float4 o;
    o.x = (a.x + b.x) + (c.x + d.x);
    o.y = (a.y + b.y) + (c.y + d.y);
    o.z = (a.z + b.z) + (c.z + d.z);
    o.w = (a.w + b.w) + (c.w + d.w);
    ((float4*)out)[idx] = o;
}

// ---------------------------------------------------------------------------
extern "C" void kernel_launch(void* const* d_in, const int* in_sizes, int n_in,
                              void* d_out, int out_size)
{
    const float* m1   = (const float*)d_in[0];
    const float* m2   = (const float*)d_in[1];
    const float* m3   = (const float*)d_in[2];
    const float* m4   = (const float*)d_in[3];
    const float* WQ_w = (const float*)d_in[4];
    const float* WQ_b = (const float*)d_in[5];
    const float* WK_w = (const float*)d_in[6];
    const float* WK_b = (const float*)d_in[7];
    float* out = (float*)d_out;

    mlp_kernel<<<dim3(128, 5), 256>>>(m1, m2, m3, m4, WQ_w, WQ_b, WK_w, WK_b);
    scan_search_kernel<<<1028, 256>>>();
    query_kernel<<<dim3(NTILE, 4), 256>>>(m1, m2, m3, m4);
    reduce_kernel<<<(T1 * 32 / 4 + 255) / 256, 256>>>(out);
}

// round 12
// speedup vs baseline: 1.2255x; 1.0650x over previous
#include <cuda_runtime.h>

// ---------------------------------------------------------------------------
// out[i, :32] = sum_m sum_{j: t2m_j <= t1_i} (Q_i . Km_j) * Vm_j[:32]
//   Q = mlp3(m1, WQ); K_m = mlp3(m_m, WK[m]); V_m = m_m[:, :32]
// ---------------------------------------------------------------------------

#define T1        4096
#define TOTK      22528            // 4096+6144+8192+4096
#define CBLK      64               // key block size
#define NOBLK     352              // total key blocks (64+96+128+64)
#define NSTATE    356              // exclusive prefix states (nb+1 per modality)
#define NTILE     128              // query tiles of 32

typedef unsigned long long u64;

__device__ __forceinline__ u64 pk2(float lo, float hi) {
    u64 r; asm("mov.b64 %0,{%1,%2};" : "=l"(r) : "f"(lo), "f"(hi)); return r;
}
__device__ __forceinline__ void upk2(u64 v, float& lo, float& hi) {
    asm("mov.b64 {%0,%1},%2;" : "=f"(lo), "=f"(hi) : "l"(v));
}
__device__ __forceinline__ void ffma2(u64& d, u64 a, u64 b) {
    asm("fma.rn.f32x2 %0,%1,%2,%0;" : "+l"(d) : "l"(a), "l"(b));
}

// scratch (no allocations allowed)
__device__ float g_Q[T1 * 64];
__device__ float g_K[TOTK * 64];
__device__ float g_t2[TOTK];
__device__ float g_O[NOBLK * 2048];    // per-block sums  K^T V  (64 x 32)
__device__ float g_S[NSTATE * 2048];   // exclusive prefix states
__device__ float g_P[4][T1 * 32];      // per-modality partial outputs
__device__ int   g_cnt[NTILE][4][2];

__constant__ int c_T2[4]    = {4096, 6144, 8192, 4096};
__constant__ int c_KOFF[4]  = {0, 4096, 10240, 18432};
__constant__ int c_NB[4]    = {64, 96, 128, 64};
__constant__ int c_OOFF[5]  = {0, 64, 160, 288, 352};
__constant__ int c_SOFF[4]  = {0, 65, 162, 291};

// ---------------------------------------------------------------------------
// Kernel 1: fused 3-layer MLP + (for K tasks) per-block outer-product sums.
// Software-pipelined: next layer's weights (and the blocksum V tile) are
// prefetched into registers BEFORE each compute loop, so the LDG latency
// hides under ~900 instructions of FMA work instead of stalling at a sync.
// ---------------------------------------------------------------------------
__global__ void __launch_bounds__(256) mlp_kernel(
    const float* __restrict__ m1, const float* __restrict__ m2,
    const float* __restrict__ m3, const float* __restrict__ m4,
    const float* __restrict__ WQ_w, const float* __restrict__ WQ_b,
    const float* __restrict__ WK_w, const float* __restrict__ WK_b)
{
    __shared__ float Hs[64][68];   // [k][row] transposed activations; later V
    __shared__ float Ws[64][68];   // [k][col] weights; later K tile [j][d]
    __shared__ float bsAll[192];   // all 3 bias rows

    const int task = blockIdx.y;
    const int rowsTab[5] = {4096, 4096, 6144, 8192, 4096};
    const int rows = rowsTab[task];
    const int row0 = blockIdx.x * 64;
    if (row0 >= rows) return;

    const float* X;
    if (task <= 1)      X = m1;
    else if (task == 2) X = m2;
    else if (task == 3) X = m3;
    else                X = m4;

    const float* Wb; const float* bb; float* out;
    if (task == 0) { Wb = WQ_w; bb = WQ_b; out = g_Q; }
    else {
        int m = task - 1;
        Wb = WK_w + m * 3 * 4096;
        bb = WK_b + m * 192;
        out = g_K + c_KOFF[m] * 64;
    }

    const int tid = threadIdx.x;
    // prologue: X tile (transposed), layer-0 weights, all biases, t2 extract
    for (int idx = tid; idx < 4096; idx += 256) {
        int r = idx >> 6, c = idx & 63;
        Hs[c][r] = X[(row0 + r) * 64 + c];
    }
    for (int idx = tid; idx < 4096; idx += 256)
        Ws[idx >> 6][idx & 63] = Wb[idx];
    if (tid < 192) bsAll[tid] = bb[tid];
    if (task > 0 && tid < 64)
        g_t2[c_KOFF[task - 1] + row0 + tid] = X[(row0 + tid) * 64 + 63];
    __syncthreads();

    const int r0 = (tid & 15) * 4;     // 16 row groups
    const int c0 = (tid >> 4) * 4;     // 16 col groups
    float wreg[16];
    float vreg[8];

    for (int l = 0; l < 3; l++) {
        // prefetch next phase's global data (overlaps with compute below)
        if (l < 2) {
            #pragma unroll
            for (int q = 0; q < 16; q++)
                wreg[q] = Wb[(l + 1) * 4096 + tid + q * 256];
        } else if (task > 0) {
            #pragma unroll
            for (int q = 0; q < 8; q++) {
                int idx = tid + q * 256;
                vreg[q] = X[(row0 + (idx >> 5)) * 64 + (idx & 31)];
            }
        }

        u64 acc[4][2];   // [row][col-pair]
        #pragma unroll
        for (int rr = 0; rr < 4; rr++)
            #pragma unroll
            for (int cp = 0; cp < 2; cp++)
                acc[rr][cp] = pk2(bsAll[l * 64 + c0 + 2 * cp],
                                  bsAll[l * 64 + c0 + 2 * cp + 1]);

        #pragma unroll 8
        for (int k = 0; k < 64; k++) {
            float4 h = *(const float4*)&Hs[k][r0];
            ulonglong2 w2 = *(const ulonglong2*)&Ws[k][c0];
            u64 hd0 = pk2(h.x, h.x), hd1 = pk2(h.y, h.y);
            u64 hd2 = pk2(h.z, h.z), hd3 = pk2(h.w, h.w);
            ffma2(acc[0][0], hd0, w2.x); ffma2(acc[0][1], hd0, w2.y);
            ffma2(acc[1][0], hd1, w2.x); ffma2(acc[1][1], hd1, w2.y);
            ffma2(acc[2][0], hd2, w2.x); ffma2(acc[2][1], hd2, w2.y);
            ffma2(acc[3][0], hd3, w2.x); ffma2(acc[3][1], hd3, w2.y);
        }

        float a[4][4];
        #pragma unroll
        for (int rr = 0; rr < 4; rr++)
            #pragma unroll
            for (int cp = 0; cp < 2; cp++)
                upk2(acc[rr][cp], a[rr][2 * cp], a[rr][2 * cp + 1]);

        if (l < 2) {
            #pragma unroll
            for (int rr = 0; rr < 4; rr++)
                #pragma unroll
                for (int cc = 0; cc < 4; cc++) a[rr][cc] = fmaxf(a[rr][cc], 0.0f);
        }
        __syncthreads();   // all reads of Hs/Ws for layer l done

        if (l < 2) {
            #pragma unroll
            for (int cc = 0; cc < 4; cc++) {
                float4 v = make_float4(a[0][cc], a[1][cc], a[2][cc], a[3][cc]);
                *(float4*)&Hs[c0 + cc][r0] = v;
            }
            #pragma unroll
            for (int q = 0; q < 16; q++) {
                int idx = tid + q * 256;
                Ws[idx >> 6][idx & 63] = wreg[q];
            }
            __syncthreads();
        } else {
            #pragma unroll
            for (int rr = 0; rr < 4; rr++) {
                float4 v = make_float4(a[rr][0], a[rr][1], a[rr][2], a[rr][3]);
                *(float4*)&out[(row0 + r0 + rr) * 64 + c0] = v;
                if (task > 0) *(float4*)&Ws[r0 + rr][c0] = v;   // K tile [j][d]
            }
            if (task > 0) {
                #pragma unroll
                for (int q = 0; q < 8; q++) {
                    int idx = tid + q * 256;
                    Hs[idx >> 5][idx & 31] = vreg[q];           // V tile [j][e]
                }
            }
            __syncthreads();
        }
    }

    if (task == 0) return;

    // ---------------- fused blocksum: O_b = K^T V ----------
    const int m = task - 1;
    const int d1 = tid & 63;
    const int gg = tid >> 6;   // 0..3 -> e0 = gg*8
    u64 acc2[4] = {0ULL, 0ULL, 0ULL, 0ULL};

    #pragma unroll 8
    for (int j = 0; j < CBLK; j++) {
        float kv = Ws[j][d1];
        u64 kd = pk2(kv, kv);
        ulonglong2 va = *(const ulonglong2*)&Hs[j][gg * 8];
        ulonglong2 vb = *(const ulonglong2*)&Hs[j][gg * 8 + 4];
        ffma2(acc2[0], kd, va.x); ffma2(acc2[1], kd, va.y);
        ffma2(acc2[2], kd, vb.x); ffma2(acc2[3], kd, vb.y);
    }
    float a2[8];
    upk2(acc2[0], a2[0], a2[1]); upk2(acc2[1], a2[2], a2[3]);
    upk2(acc2[2], a2[4], a2[5]); upk2(acc2[3], a2[6], a2[7]);
    const int blk = c_OOFF[m] + (row0 >> 6);
    float* o = &g_O[blk * 2048 + d1 * 32 + gg * 8];
    *(float4*)o       = make_float4(a2[0], a2[1], a2[2], a2[3]);
    *(float4*)(o + 4) = make_float4(a2[4], a2[5], a2[6], a2[7]);
}

// ---------------------------------------------------------------------------
// Kernel 2: warp-parallel exclusive scan + tile binary searches.
// ---------------------------------------------------------------------------
__global__ void __launch_bounds__(256) scan_search_kernel()
{
    const int blk = blockIdx.x;
    if (blk < 1024) {
        const int gw   = blk * 8 + (threadIdx.x >> 5);   // 0..8191
        const int lane = threadIdx.x & 31;
        const int m    = gw >> 11;
        const int el   = gw & 2047;
        const int nb   = c_NB[m];
        const int q    = nb >> 5;                        // 2,3,4,2
        const float* src = &g_O[c_OOFF[m] * 2048 + el];
        float* dst       = &g_S[c_SOFF[m] * 2048 + el];
        const int b0 = lane * q;

        float v[4];
        #pragma unroll
        for (int b = 0; b < 4; b++)
            v[b] = (b < q) ? src[(b0 + b) * 2048] : 0.0f;
        float s = 0.0f;
        #pragma unroll
        for (int b = 0; b < 4; b++) if (b < q) s += v[b];

        float incl = s;
        #pragma unroll
        for (int off = 1; off < 32; off <<= 1) {
            float t = __shfl_up_sync(0xffffffffu, incl, off);
            if (lane >= off) incl += t;
        }
        float run = incl - s;

        #pragma unroll
        for (int b = 0; b < 4; b++) {
            if (b < q) { dst[(b0 + b) * 2048] = run; run += v[b]; }
        }
        if (lane == 31) dst[nb * 2048] = run;
    } else {
        const int sid = (blk - 1024) * 256 + threadIdx.x;   // 0..1023
        const int tile = sid >> 3;
        const int m    = (sid >> 1) & 3;
        const int w    = sid & 1;
        const float target = g_t2[tile * 32 + (w ? 31 : 0)];
        const int ko = c_KOFF[m];
        int lo = 0, hi = c_T2[m];
        while (lo < hi) {
            int mid = (lo + hi) >> 1;
            if (g_t2[ko + mid] <= target) lo = mid + 1; else hi = mid;
        }
        g_cnt[tile][m][w] = lo;
    }
}

// ---------------------------------------------------------------------------
// Kernel 3: query kernel, pair-packed (R11 measured config).
// ---------------------------------------------------------------------------
__global__ void __launch_bounds__(256) query_kernel(
    const float* __restrict__ m1, const float* __restrict__ m2,
    const float* __restrict__ m3, const float* __restrict__ m4)
{
    __shared__ float Qs [32][68];    // [i][d]
    __shared__ float Ss2[32][68];    // state transposed [e][d]
    __shared__ float Ks [64][68];    // keys [j][d]
    __shared__ float Vs2[32][68];    // values transposed [e][j]
    __shared__ float sc [32][68];    // scores [i][j]
    __shared__ float t2s[64];

    const int tid = threadIdx.x;
    const int i   = tid & 31;        // query (lane)
    const int g   = tid >> 5;        // warp
    const int e0  = g * 4;           // e-slice for matvec/accumulate
    const int j0  = g * 8;           // j-slice for scores
    const int tile = blockIdx.x;
    const int m    = blockIdx.y;
    const int i0   = tile * 32;

    const float* X;
    if (m == 0) X = m1; else if (m == 1) X = m2; else if (m == 2) X = m3; else X = m4;
    const int ko = c_KOFF[m];

    const int cf = g_cnt[tile][m][0];
    const int cl = g_cnt[tile][m][1];
    const int B0 = cf >> 6;
    const int jstart = B0 << 6;
    const int jend = cl;

    for (int idx = tid; idx < 2048; idx += 256) {
        int r = idx >> 6, d = idx & 63;
        Qs[r][d] = g_Q[(i0 + r) * 64 + d];
    }
    const float* Sp = &g_S[(c_SOFF[m] + B0) * 2048];
    for (int idx = tid; idx < 2048; idx += 256) {
        int d = idx >> 5, e = idx & 31;
        Ss2[e][d] = Sp[idx];
    }
    const float t1i = g_t2[i0 + i];
    __syncthreads();

    u64 accp[4] = {0ULL, 0ULL, 0ULL, 0ULL};

    // state matvec: acc[e] += sum_d Q[i][d] * S[d][e], packed over d
    #pragma unroll 4
    for (int dp = 0; dp < 16; dp++) {
        ulonglong2 q2 = *(const ulonglong2*)&Qs[i][dp * 4];
        #pragma unroll
        for (int e = 0; e < 4; e++) {
            ulonglong2 s2 = *(const ulonglong2*)&Ss2[e0 + e][dp * 4];
            ffma2(accp[e], q2.x, s2.x);
            ffma2(accp[e], q2.y, s2.y);
        }
    }

    for (int jc = jstart; jc < jend; jc += 64) {
        const int nj = min(64, jend - jc);
        __syncthreads();
        for (int idx = tid; idx < 4096; idx += 256) {
            int j = idx >> 6, d = idx & 63;
            Ks[j][d] = (j < nj) ? g_K[(ko + jc + j) * 64 + d] : 0.0f;
        }
        for (int idx = tid; idx < 2048; idx += 256) {
            int j = idx >> 5, e = idx & 31;
            Vs2[e][j] = (j < nj) ? X[(jc + j) * 64 + e] : 0.0f;
        }
        if (tid < 64) t2s[tid] = (tid < nj) ? g_t2[ko + jc + tid] : 3.0e38f;
        __syncthreads();

        u64 sp[8];
        #pragma unroll
        for (int jj = 0; jj < 8; jj++) sp[jj] = 0ULL;
        #pragma unroll 4
        for (int dp = 0; dp < 16; dp++) {
            ulonglong2 q2 = *(const ulonglong2*)&Qs[i][dp * 4];
            #pragma unroll
            for (int jj = 0; jj < 8; jj++) {
                ulonglong2 k2 = *(const ulonglong2*)&Ks[j0 + jj][dp * 4];
                ffma2(sp[jj], q2.x, k2.x);
                ffma2(sp[jj], q2.y, k2.y);
            }
        }
        #pragma unroll
        for (int jj = 0; jj < 8; jj++) {
            float slo, shi;
            upk2(sp[jj], slo, shi);
            float s = slo + shi;
            sc[i][j0 + jj] = (t2s[j0 + jj] <= t1i) ? s : 0.0f;
        }
        __syncthreads();

        #pragma unroll 4
        for (int jp = 0; jp < 16; jp++) {
            ulonglong2 s2 = *(const ulonglong2*)&sc[i][jp * 4];
            #pragma unroll
            for (int e = 0; e < 4; e++) {
                ulonglong2 v2 = *(const ulonglong2*)&Vs2[e0 + e][jp * 4];
                ffma2(accp[e], s2.x, v2.x);
                ffma2(accp[e], s2.y, v2.y);
            }
        }
    }

    float av[4];
    #pragma unroll
    for (int e = 0; e < 4; e++) {
        float lo, hi;
        upk2(accp[e], lo, hi);
        av[e] = lo + hi;
    }
    *(float4*)&g_P[m][(i0 + i) * 32 + e0] = make_float4(av[0], av[1], av[2], av[3]);
}

// ---------------------------------------------------------------------------
// Kernel 4: sum the 4 per-modality partials into the output.
// ---------------------------------------------------------------------------
__global__ void __launch_bounds__(128) reduce_kernel(float* __restrict__ out)
{
    const int idx = (blockIdx.x * 128 + threadIdx.x);
    if (idx >= T1 * 32 / 4) return;
    float4 a = ((const float4*)g_P[0])[idx];
    float4 b = ((const float4*)g_P[1])[idx];
    float4 c = ((const float4*)g_P[2])[idx];
    float4 d = ((const float4*)g_P[3])[idx];
    float4 o;
    o.x = (a.x + b.x) + (c.x + d.x);
    o.y = (a.y + b.y) + (c.y + d.y);
    o.z = (a.z + b.z) + (c.z + d.z);
    o.w = (a.w + b.w) + (c.w + d.w);
    ((float4*)out)[idx] = o;
}

// ---------------------------------------------------------------------------
extern "C" void kernel_launch(void* const* d_in, const int* in_sizes, int n_in,
                              void* d_out, int out_size)
{
    const float* m1   = (const float*)d_in[0];
    const float* m2   = (const float*)d_in[1];
    const float* m3   = (const float*)d_in[2];
    const float* m4   = (const float*)d_in[3];
    const float* WQ_w = (const float*)d_in[4];
    const float* WQ_b = (const float*)d_in[5];
    const float* WK_w = (const float*)d_in[6];
    const float* WK_b = (const float*)d_in[7];
    float* out = (float*)d_out;

    mlp_kernel<<<dim3(128, 5), 256>>>(m1, m2, m3, m4, WQ_w, WQ_b, WK_w, WK_b);
    scan_search_kernel<<<1028, 256>>>();
    query_kernel<<<dim3(NTILE, 4), 256>>>(m1, m2, m3, m4);
    reduce_kernel<<<(T1 * 32 / 4 + 127) / 128, 128>>>(out);
}

// round 13
// speedup vs baseline: 1.3218x; 1.0786x over previous
#include <cuda_runtime.h>

// ---------------------------------------------------------------------------
// out[i, :32] = sum_m sum_{j: t2m_j <= t1_i} (Q_i . Km_j) * Vm_j[:32]
//   Q = mlp3(m1, WQ); K_m = mlp3(m_m, WK[m]); V_m = m_m[:, :32]
// ---------------------------------------------------------------------------

#define T1        4096
#define TOTK      22528            // 4096+6144+8192+4096
#define CBLK      64               // key block size
#define NOBLK     352              // total key blocks (64+96+128+64)
#define NSTATE    356              // exclusive prefix states (nb+1 per modality)
#define NTILE     128              // query tiles of 32

typedef unsigned long long u64;

__device__ __forceinline__ u64 pk2(float lo, float hi) {
    u64 r; asm("mov.b64 %0,{%1,%2};" : "=l"(r) : "f"(lo), "f"(hi)); return r;
}
__device__ __forceinline__ void upk2(u64 v, float& lo, float& hi) {
    asm("mov.b64 {%0,%1},%2;" : "=f"(lo), "=f"(hi) : "l"(v));
}
__device__ __forceinline__ void ffma2(u64& d, u64 a, u64 b) {
    asm("fma.rn.f32x2 %0,%1,%2,%0;" : "+l"(d) : "l"(a), "l"(b));
}

// scratch (no allocations allowed)
__device__ float g_Q[T1 * 64];
__device__ float g_K[TOTK * 64];
__device__ float g_t2[TOTK];
__device__ float g_O[NOBLK * 2048];    // per-block sums  K^T V  (64 x 32)
__device__ float g_S[NSTATE * 2048];   // exclusive prefix states
__device__ int   g_cnt[NTILE][4][2];

__constant__ int c_T2[4]    = {4096, 6144, 8192, 4096};
__constant__ int c_KOFF[4]  = {0, 4096, 10240, 18432};
__constant__ int c_NB[4]    = {64, 96, 128, 64};
__constant__ int c_OOFF[5]  = {0, 64, 160, 288, 352};
__constant__ int c_SOFF[4]  = {0, 65, 162, 291};

// ---------------------------------------------------------------------------
// Kernel 1: fused 3-layer MLP + (for K tasks) blocksum O_b = K^T V, t2.
// 128 threads/block, 64-row tile, 4 rows x 8 cols per thread (LDS:FMA cycle
// ratio 1.5 vs 2.0 for 4x4). Software-pipelined weight/V prefetch retained.
// ---------------------------------------------------------------------------
__global__ void __launch_bounds__(128) mlp_kernel(
    const float* __restrict__ m1, const float* __restrict__ m2,
    const float* __restrict__ m3, const float* __restrict__ m4,
    const float* __restrict__ WQ_w, const float* __restrict__ WQ_b,
    const float* __restrict__ WK_w, const float* __restrict__ WK_b)
{
    __shared__ float Hs[64][68];   // [k][row] transposed activations; later V
    __shared__ float Ws[64][68];   // [k][col] weights; later K tile [j][d]
    __shared__ float bsAll[192];   // all 3 bias rows

    const int task = blockIdx.y;
    const int rowsTab[5] = {4096, 4096, 6144, 8192, 4096};
    const int rows = rowsTab[task];
    const int row0 = blockIdx.x * 64;
    if (row0 >= rows) return;

    const float* X;
    if (task <= 1)      X = m1;
    else if (task == 2) X = m2;
    else if (task == 3) X = m3;
    else                X = m4;

    const float* Wb; const float* bb; float* out;
    if (task == 0) { Wb = WQ_w; bb = WQ_b; out = g_Q; }
    else {
        int m = task - 1;
        Wb = WK_w + m * 3 * 4096;
        bb = WK_b + m * 192;
        out = g_K + c_KOFF[m] * 64;
    }

    const int tid = threadIdx.x;
    // prologue
    for (int idx = tid; idx < 4096; idx += 128) {
        int r = idx >> 6, c = idx & 63;
        Hs[c][r] = X[(row0 + r) * 64 + c];
    }
    for (int idx = tid; idx < 4096; idx += 128)
        Ws[idx >> 6][idx & 63] = Wb[idx];
    for (int idx = tid; idx < 192; idx += 128) bsAll[idx] = bb[idx];
    if (task > 0 && tid < 64)
        g_t2[c_KOFF[task - 1] + row0 + tid] = X[(row0 + tid) * 64 + 63];
    __syncthreads();

    const int r0 = (tid & 15) * 4;     // 16 row groups of 4
    const int c0 = (tid >> 4) * 8;     // 8 col groups of 8
    float wreg[32];
    float vreg[16];

    for (int l = 0; l < 3; l++) {
        // prefetch next phase's global data (overlaps with compute below)
        if (l < 2) {
            #pragma unroll
            for (int q = 0; q < 32; q++)
                wreg[q] = Wb[(l + 1) * 4096 + tid + q * 128];
        } else if (task > 0) {
            #pragma unroll
            for (int q = 0; q < 16; q++) {
                int idx = tid + q * 128;
                vreg[q] = X[(row0 + (idx >> 5)) * 64 + (idx & 31)];
            }
        }

        u64 acc[4][4];   // [row][col-pair]
        #pragma unroll
        for (int rr = 0; rr < 4; rr++)
            #pragma unroll
            for (int cp = 0; cp < 4; cp++)
                acc[rr][cp] = pk2(bsAll[l * 64 + c0 + 2 * cp],
                                  bsAll[l * 64 + c0 + 2 * cp + 1]);

        #pragma unroll 8
        for (int k = 0; k < 64; k++) {
            float4 h = *(const float4*)&Hs[k][r0];
            ulonglong2 wa = *(const ulonglong2*)&Ws[k][c0];
            ulonglong2 wb2 = *(const ulonglong2*)&Ws[k][c0 + 4];
            u64 hd0 = pk2(h.x, h.x), hd1 = pk2(h.y, h.y);
            u64 hd2 = pk2(h.z, h.z), hd3 = pk2(h.w, h.w);
            ffma2(acc[0][0], hd0, wa.x); ffma2(acc[0][1], hd0, wa.y);
            ffma2(acc[0][2], hd0, wb2.x); ffma2(acc[0][3], hd0, wb2.y);
            ffma2(acc[1][0], hd1, wa.x); ffma2(acc[1][1], hd1, wa.y);
            ffma2(acc[1][2], hd1, wb2.x); ffma2(acc[1][3], hd1, wb2.y);
            ffma2(acc[2][0], hd2, wa.x); ffma2(acc[2][1], hd2, wa.y);
            ffma2(acc[2][2], hd2, wb2.x); ffma2(acc[2][3], hd2, wb2.y);
            ffma2(acc[3][0], hd3, wa.x); ffma2(acc[3][1], hd3, wa.y);
            ffma2(acc[3][2], hd3, wb2.x); ffma2(acc[3][3], hd3, wb2.y);
        }

        float a[4][8];
        #pragma unroll
        for (int rr = 0; rr < 4; rr++)
            #pragma unroll
            for (int cp = 0; cp < 4; cp++)
                upk2(acc[rr][cp], a[rr][2 * cp], a[rr][2 * cp + 1]);

        if (l < 2) {
            #pragma unroll
            for (int rr = 0; rr < 4; rr++)
                #pragma unroll
                for (int cc = 0; cc < 8; cc++) a[rr][cc] = fmaxf(a[rr][cc], 0.0f);
        }
        __syncthreads();   // all reads of Hs/Ws for layer l done

        if (l < 2) {
            #pragma unroll
            for (int cc = 0; cc < 8; cc++) {
                float4 v = make_float4(a[0][cc], a[1][cc], a[2][cc], a[3][cc]);
                *(float4*)&Hs[c0 + cc][r0] = v;
            }
            #pragma unroll
            for (int q = 0; q < 32; q++) {
                int idx = tid + q * 128;
                Ws[idx >> 6][idx & 63] = wreg[q];
            }
            __syncthreads();
        } else {
            #pragma unroll
            for (int rr = 0; rr < 4; rr++) {
                float4 va = make_float4(a[rr][0], a[rr][1], a[rr][2], a[rr][3]);
                float4 vb = make_float4(a[rr][4], a[rr][5], a[rr][6], a[rr][7]);
                *(float4*)&out[(row0 + r0 + rr) * 64 + c0]     = va;
                *(float4*)&out[(row0 + r0 + rr) * 64 + c0 + 4] = vb;
                if (task > 0) {
                    *(float4*)&Ws[r0 + rr][c0]     = va;   // K tile [j][d]
                    *(float4*)&Ws[r0 + rr][c0 + 4] = vb;
                }
            }
            if (task > 0) {
                #pragma unroll
                for (int q = 0; q < 16; q++) {
                    int idx = tid + q * 128;
                    Hs[idx >> 5][idx & 31] = vreg[q];       // V tile [j][e]
                }
            }
            __syncthreads();
        }
    }

    if (task == 0) return;

    // ---------------- fused blocksum: O_b = K^T V ----------
    const int m = task - 1;
    const int d1 = tid & 63;
    const int gg = tid >> 6;   // 0..1 -> e0 = gg*16
    const int e0 = gg * 16;
    u64 acc2[8];
    #pragma unroll
    for (int p = 0; p < 8; p++) acc2[p] = 0ULL;

    #pragma unroll 8
    for (int j = 0; j < CBLK; j++) {
        float kv = Ws[j][d1];
        u64 kd = pk2(kv, kv);
        ulonglong2 va = *(const ulonglong2*)&Hs[j][e0];
        ulonglong2 vb = *(const ulonglong2*)&Hs[j][e0 + 4];
        ulonglong2 vc = *(const ulonglong2*)&Hs[j][e0 + 8];
        ulonglong2 vd = *(const ulonglong2*)&Hs[j][e0 + 12];
        ffma2(acc2[0], kd, va.x); ffma2(acc2[1], kd, va.y);
        ffma2(acc2[2], kd, vb.x); ffma2(acc2[3], kd, vb.y);
        ffma2(acc2[4], kd, vc.x); ffma2(acc2[5], kd, vc.y);
        ffma2(acc2[6], kd, vd.x); ffma2(acc2[7], kd, vd.y);
    }
    float a2[16];
    #pragma unroll
    for (int p = 0; p < 8; p++) upk2(acc2[p], a2[2 * p], a2[2 * p + 1]);
    const int blk = c_OOFF[m] + (row0 >> 6);
    float* o = &g_O[blk * 2048 + d1 * 32 + e0];
    #pragma unroll
    for (int q = 0; q < 4; q++)
        *(float4*)(o + q * 4) = make_float4(a2[4*q], a2[4*q+1], a2[4*q+2], a2[4*q+3]);
}

// ---------------------------------------------------------------------------
// Kernel 2: warp-parallel exclusive scan (blocks 0..1023) + tile binary
// searches (1024..1027) + output zero-fill (1028..1155).
// ---------------------------------------------------------------------------
__global__ void __launch_bounds__(256) scan_search_kernel(float* __restrict__ out)
{
    const int blk = blockIdx.x;
    if (blk < 1024) {
        const int gw   = blk * 8 + (threadIdx.x >> 5);   // 0..8191
        const int lane = threadIdx.x & 31;
        const int m    = gw >> 11;
        const int el   = gw & 2047;
        const int nb   = c_NB[m];
        const int q    = nb >> 5;                        // 2,3,4,2
        const float* src = &g_O[c_OOFF[m] * 2048 + el];
        float* dst       = &g_S[c_SOFF[m] * 2048 + el];
        const int b0 = lane * q;

        float v[4];
        #pragma unroll
        for (int b = 0; b < 4; b++)
            v[b] = (b < q) ? src[(b0 + b) * 2048] : 0.0f;
        float s = 0.0f;
        #pragma unroll
        for (int b = 0; b < 4; b++) if (b < q) s += v[b];

        float incl = s;
        #pragma unroll
        for (int off = 1; off < 32; off <<= 1) {
            float t = __shfl_up_sync(0xffffffffu, incl, off);
            if (lane >= off) incl += t;
        }
        float run = incl - s;

        #pragma unroll
        for (int b = 0; b < 4; b++) {
            if (b < q) { dst[(b0 + b) * 2048] = run; run += v[b]; }
        }
        if (lane == 31) dst[nb * 2048] = run;
    } else if (blk < 1028) {
        const int sid = (blk - 1024) * 256 + threadIdx.x;   // 0..1023
        const int tile = sid >> 3;
        const int m    = (sid >> 1) & 3;
        const int w    = sid & 1;
        const float target = g_t2[tile * 32 + (w ? 31 : 0)];
        const int ko = c_KOFF[m];
        int lo = 0, hi = c_T2[m];
        while (lo < hi) {
            int mid = (lo + hi) >> 1;
            if (g_t2[ko + mid] <= target) lo = mid + 1; else hi = mid;
        }
        g_cnt[tile][m][w] = lo;
    } else {
        const int idx = (blk - 1028) * 256 + threadIdx.x;   // float4 index
        if (idx < T1 * 32 / 4)
            ((float4*)out)[idx] = make_float4(0.f, 0.f, 0.f, 0.f);
    }
}

// ---------------------------------------------------------------------------
// Kernel 3: query kernel, pair-packed (R11/12 measured config), writing
// directly into out via atomicAdd (replaces reduce kernel + g_P).
// ---------------------------------------------------------------------------
__global__ void __launch_bounds__(256) query_kernel(
    const float* __restrict__ m1, const float* __restrict__ m2,
    const float* __restrict__ m3, const float* __restrict__ m4,
    float* __restrict__ out)
{
    __shared__ float Qs [32][68];    // [i][d]
    __shared__ float Ss2[32][68];    // state transposed [e][d]
    __shared__ float Ks [64][68];    // keys [j][d]
    __shared__ float Vs2[32][68];    // values transposed [e][j]
    __shared__ float sc [32][68];    // scores [i][j]
    __shared__ float t2s[64];

    const int tid = threadIdx.x;
    const int i   = tid & 31;        // query (lane)
    const int g   = tid >> 5;        // warp
    const int e0  = g * 4;           // e-slice for matvec/accumulate
    const int j0  = g * 8;           // j-slice for scores
    const int tile = blockIdx.x;
    const int m    = blockIdx.y;
    const int i0   = tile * 32;

    const float* X;
    if (m == 0) X = m1; else if (m == 1) X = m2; else if (m == 2) X = m3; else X = m4;
    const int ko = c_KOFF[m];

    const int cf = g_cnt[tile][m][0];
    const int cl = g_cnt[tile][m][1];
    const int B0 = cf >> 6;
    const int jstart = B0 << 6;
    const int jend = cl;

    for (int idx = tid; idx < 2048; idx += 256) {
        int r = idx >> 6, d = idx & 63;
        Qs[r][d] = g_Q[(i0 + r) * 64 + d];
    }
    const float* Sp = &g_S[(c_SOFF[m] + B0) * 2048];
    for (int idx = tid; idx < 2048; idx += 256) {
        int d = idx >> 5, e = idx & 31;
        Ss2[e][d] = Sp[idx];
    }
    const float t1i = g_t2[i0 + i];
    __syncthreads();

    u64 accp[4] = {0ULL, 0ULL, 0ULL, 0ULL};

    // state matvec: acc[e] += sum_d Q[i][d] * S[d][e], packed over d
    #pragma unroll 4
    for (int dp = 0; dp < 16; dp++) {
        ulonglong2 q2 = *(const ulonglong2*)&Qs[i][dp * 4];
        #pragma unroll
        for (int e = 0; e < 4; e++) {
            ulonglong2 s2 = *(const ulonglong2*)&Ss2[e0 + e][dp * 4];
            ffma2(accp[e], q2.x, s2.x);
            ffma2(accp[e], q2.y, s2.y);
        }
    }

    for (int jc = jstart; jc < jend; jc += 64) {
        const int nj = min(64, jend - jc);
        __syncthreads();
        for (int idx = tid; idx < 4096; idx += 256) {
            int j = idx >> 6, d = idx & 63;
            Ks[j][d] = (j < nj) ? g_K[(ko + jc + j) * 64 + d] : 0.0f;
        }
        for (int idx = tid; idx < 2048; idx += 256) {
            int j = idx >> 5, e = idx & 31;
            Vs2[e][j] = (j < nj) ? X[(jc + j) * 64 + e] : 0.0f;
        }
        if (tid < 64) t2s[tid] = (tid < nj) ? g_t2[ko + jc + tid] : 3.0e38f;
        __syncthreads();

        u64 sp[8];
        #pragma unroll
        for (int jj = 0; jj < 8; jj++) sp[jj] = 0ULL;
        #pragma unroll 4
        for (int dp = 0; dp < 16; dp++) {
            ulonglong2 q2 = *(const ulonglong2*)&Qs[i][dp * 4];
            #pragma unroll
            for (int jj = 0; jj < 8; jj++) {
                ulonglong2 k2 = *(const ulonglong2*)&Ks[j0 + jj][dp * 4];
                ffma2(sp[jj], q2.x, k2.x);
                ffma2(sp[jj], q2.y, k2.y);
            }
        }
        #pragma unroll
        for (int jj = 0; jj < 8; jj++) {
            float slo, shi;
            upk2(sp[jj], slo, shi);
            float s = slo + shi;
            sc[i][j0 + jj] = (t2s[j0 + jj] <= t1i) ? s : 0.0f;
        }
        __syncthreads();

        #pragma unroll 4
        for (int jp = 0; jp < 16; jp++) {
            ulonglong2 s2 = *(const ulonglong2*)&sc[i][jp * 4];
            #pragma unroll
            for (int e = 0; e < 4; e++) {
                ulonglong2 v2 = *(const ulonglong2*)&Vs2[e0 + e][jp * 4];
                ffma2(accp[e], s2.x, v2.x);
                ffma2(accp[e], s2.y, v2.y);
            }
        }
    }

    float* op = &out[(i0 + i) * 32 + e0];
    #pragma unroll
    for (int e = 0; e < 4; e++) {
        float lo, hi;
        upk2(accp[e], lo, hi);
        atomicAdd(op + e, lo + hi);
    }
}

// ---------------------------------------------------------------------------
extern "C" void kernel_launch(void* const* d_in, const int* in_sizes, int n_in,
                              void* d_out, int out_size)
{
    const float* m1   = (const float*)d_in[0];
    const float* m2   = (const float*)d_in[1];
    const float* m3   = (const float*)d_in[2];
    const float* m4   = (const float*)d_in[3];
    const float* WQ_w = (const float*)d_in[4];
    const float* WQ_b = (const float*)d_in[5];
    const float* WK_w = (const float*)d_in[6];
    const float* WK_b = (const float*)d_in[7];
    float* out = (float*)d_out;

    mlp_kernel<<<dim3(128, 5), 128>>>(m1, m2, m3, m4, WQ_w, WQ_b, WK_w, WK_b);
    scan_search_kernel<<<1156, 256>>>(out);
    query_kernel<<<dim3(NTILE, 4), 256>>>(m1, m2, m3, m4, out);
}